// round 12
// baseline (speedup 1.0000x reference)
#include <cuda_runtime.h>
#include <cuda_bf16.h>
#include <cuda_fp16.h>
#include <math.h>
#include <stdint.h>

#define B_   64
#define L_   2048
#define E_   512
#define Q_   256
#define NEGV -1000000000.0f
#define EPS_ 1e-5f
#define NSPLIT 32

// ---------------------------------------------------------------------------
// device scratch (no allocations allowed)
// ---------------------------------------------------------------------------
__device__ float g_qproj[B_ * E_];
__device__ float g_ctx_part[B_ * NSPLIT * E_];
__device__ __align__(16) __half g_Wt16[E_ * E_];   // W1[:E]^T fp16 [e][k]
__device__ int g_dummy_sink;

// ---------------------------------------------------------------------------
// PTX helpers
// ---------------------------------------------------------------------------
__device__ __forceinline__ uint32_t smem_u32_of(const void* p) {
    uint32_t a;
    asm("{ .reg .u64 t; cvta.to.shared.u64 t, %1; cvt.u32.u64 %0, t; }"
        : "=r"(a) : "l"(p));
    return a;
}

__device__ __forceinline__ void ldsm4(uint32_t* r, uint32_t addr) {
    asm volatile("ldmatrix.sync.aligned.m8n8.x4.shared.b16 {%0,%1,%2,%3}, [%4];"
                 : "=r"(r[0]), "=r"(r[1]), "=r"(r[2]), "=r"(r[3]) : "r"(addr));
}

__device__ __forceinline__ void mma_f16(float* c, const uint32_t* a, const uint32_t* b) {
    asm volatile(
        "mma.sync.aligned.m16n8k16.row.col.f32.f16.f16.f32 "
        "{%0,%1,%2,%3}, {%4,%5,%6,%7}, {%8,%9}, {%0,%1,%2,%3};"
        : "+f"(c[0]), "+f"(c[1]), "+f"(c[2]), "+f"(c[3])
        : "r"(a[0]), "r"(a[1]), "r"(a[2]), "r"(a[3]), "r"(b[0]), "r"(b[1]));
}

#define CP_ASYNC16(dst, src) \
    asm volatile("cp.async.cg.shared.global [%0], [%1], 16;" :: "r"(dst), "l"(src) : "memory")
#define CP_COMMIT()  asm volatile("cp.async.commit_group;" ::: "memory")
#define CP_WAITG0()  asm volatile("cp.async.wait_group 0;" ::: "memory")

// ---------------------------------------------------------------------------
// MUFU tanh: ex2.approx + rcp.approx (both <=2 ulp). ~6 instructions.
// ---------------------------------------------------------------------------
__device__ __forceinline__ float tanh_mufu(float x) {
    float xc = fminf(fmaxf(x, -9.0f), 9.0f);
    float e;
    asm("ex2.approx.f32 %0, %1;" : "=f"(e) : "f"(xc * 2.885390081777927f)); // e^{2x}
    float r;
    asm("rcp.approx.f32 %0, %1;" : "=f"(r) : "f"(e + 1.0f));
    return (e - 1.0f) * r;
}

// ---------------------------------------------------------------------------
// Kernel 0: transpose + fp16 convert of W1[:E]
// ---------------------------------------------------------------------------
__global__ void wprep_kernel(const float* __restrict__ W1) {
    int idx = blockIdx.x * 512 + threadIdx.x;    // idx = e*512 + k
    int e = idx >> 9;
    int k = idx & 511;
    g_Wt16[idx] = __float2half_rn(W1[(size_t)k * E_ + e]);
}

// ---------------------------------------------------------------------------
// Kernel 1: qproj[b,e] = b1[e] + sum_q query[b,q] * W1[E+q, e]
// ---------------------------------------------------------------------------
__global__ void qproj_kernel(const float* __restrict__ query,
                             const float* __restrict__ W1,
                             const float* __restrict__ b1) {
    int b = blockIdx.y;
    int e = blockIdx.x * 256 + threadIdx.x;
    int tid = threadIdx.x;
    __shared__ float qs[Q_];
    qs[tid] = query[b * Q_ + tid];
    __syncthreads();
    float acc = b1[e];
#pragma unroll 8
    for (int q = 0; q < Q_; q++)
        acc = fmaf(qs[q], W1[(size_t)(E_ + q) * E_ + e], acc);
    g_qproj[b * E_ + e] = acc;
}

// ---------------------------------------------------------------------------
// Dummy pad kernel (positions logits at profiled launch index 3)
// ---------------------------------------------------------------------------
__global__ void dummy_pad_kernel() {
    if (threadIdx.x == 0) g_dummy_sink = 1;
}

// ---------------------------------------------------------------------------
// Kernel 2: tensor-core logits, fp16 x fp16, fp32 acc.
// BM=128 rows/CTA, warp tile 32m x 64n (mg 4 x ng 2): 6 ldsm : 16 mma per ks
// (0.094 B/MAC, -25% ldsm vs 32x32). A resident fp16 128KB (converted once);
// W double-buffered cp.async with precomputed bases. Early exit on masked tiles.
// ---------------------------------------------------------------------------
#define BM 128
#define NTILE 128

#define SM_W    0                       // [2 stage][128 n][128B] fp16 = 32768
#define W_STAGE 16384
#define SM_A    32768                   // [128 rows][1024B] fp16 = 131072
#define SM_QV   163840                  // 512 floats
#define SM_VV   165888                  // 512 floats
#define SM_RED  167936                  // 256 floats
#define SMEM_GEMM 169984

__global__ void __launch_bounds__(256, 1)
logits_mma_kernel(const float* __restrict__ enc,
                  const float* __restrict__ v,
                  const int* __restrict__ length,
                  float* __restrict__ logits) {
    extern __shared__ char smem[];
    uint32_t smem_b = smem_u32_of(smem);
    const int tid  = threadIdx.x;
    const int lane = tid & 31;
    const int wid  = tid >> 5;
    const int mg   = wid & 3;       // 4 M-groups of 32 rows
    const int ng   = wid >> 2;      // 2 N-groups of 64 cols

    const int bid = blockIdx.x;     // 1024 CTAs
    const int b   = bid >> 4;
    const int l0  = (bid & 15) * BM;

    // ---- early exit: fully masked tile; softmax zeroes it anyway ----
    if (l0 >= length[b]) return;

    // ---- precomputed W cp.async bases ----
    const __half* wsrc0 = g_Wt16 + (size_t)(tid >> 3) * E_ + (tid & 7) * 8;
    const uint32_t wdst0 = smem_b + SM_W + (uint32_t)(tid >> 3) * 128
                         + (((uint32_t)((tid & 7) ^ ((tid >> 3) & 7))) << 4);

    // prefetch W stage 0 (overlaps A conversion)
    {
#pragma unroll
        for (int i = 0; i < 4; i++)
            CP_ASYNC16(wdst0 + i * 4096, wsrc0 + i * 16384);
        CP_COMMIT();
    }

    // epilogue constants
    float* qv = reinterpret_cast<float*>(smem + SM_QV);
    float* vv = reinterpret_cast<float*>(smem + SM_VV);
    qv[tid]       = g_qproj[b * E_ + tid];
    qv[tid + 256] = g_qproj[b * E_ + tid + 256];
    vv[tid]       = v[tid];
    vv[tid + 256] = v[tid + 256];

    // ---- A resident: 128 rows x 512 k fp32 -> fp16, ONCE ----
    const float* Ag = enc + ((size_t)b * L_ + l0) * E_;
#pragma unroll 4
    for (int i = 0; i < 64; i++) {
        int idx = i * 256 + tid;
        int row = idx >> 7;               // 0..127
        int f4  = idx & 127;              // k0 = f4*4
        float4 a = *reinterpret_cast<const float4*>(Ag + (size_t)row * E_ + f4 * 4);
        __half2 h0 = __floats2half2_rn(a.x, a.y);
        __half2 h1 = __floats2half2_rn(a.z, a.w);
        uint32_t off = (uint32_t)(row * 1024)
                     + ((uint32_t)(((f4 >> 1) ^ (row & 7))) << 4) + (f4 & 1) * 8;
        *reinterpret_cast<__half2*>(smem + SM_A + off)     = h0;
        *reinterpret_cast<__half2*>(smem + SM_A + off + 4) = h1;
    }

    // ---- precomputed ldsm bases ----
    const int  s7     = lane & 7;
    const int  lane16 = lane >> 4;                      // 0/1
    const int  lane8  = (lane >> 3) & 1;                // 0/1
    const int  arow0  = mg * 32 + (lane & 15);
    const uint32_t abase0 = smem_b + SM_A + (uint32_t)arow0 * 1024;
    const uint32_t abase1 = abase0 + 16 * 1024;
    const int  nrb    = ng * 64 + (lane & 7) + (lane16 << 3);
    const uint32_t woff0 = (uint32_t)nrb * 128;          // j=0
    const uint32_t woff1 = woff0 + 16 * 128;             // j=1
    const uint32_t woff2 = woff0 + 32 * 128;             // j=2
    const uint32_t woff3 = woff0 + 48 * 128;             // j=3

    float acc[2][8][4];
    float lg[2][2] = {{0.f, 0.f}, {0.f, 0.f}};

    for (int nt = 0; nt < 4; nt++) {
#pragma unroll
        for (int mf = 0; mf < 2; mf++)
#pragma unroll
            for (int nf = 0; nf < 8; nf++)
#pragma unroll
                for (int e = 0; e < 4; e++) acc[mf][nf][e] = 0.0f;

#pragma unroll
        for (int kc = 0; kc < 8; kc++) {
            const int s = nt * 8 + kc;

            CP_WAITG0();
            __syncthreads();

            // issue next stage (buffer s+1 freed by the sync above)
            if (s + 1 < 32) {
                const int sn = s + 1;
                const uint32_t srcoff = (uint32_t)(sn >> 3) * 65536u
                                      + (uint32_t)(sn & 7) * 64u;   // in halfs
                const uint32_t dstb = wdst0 + (uint32_t)(sn & 1) * W_STAGE;
#pragma unroll
                for (int i = 0; i < 4; i++)
                    CP_ASYNC16(dstb + i * 4096, wsrc0 + srcoff + i * 16384);
                CP_COMMIT();
            }

            const uint32_t wBase = smem_b + SM_W + (uint32_t)(s & 1) * W_STAGE;

#pragma unroll
            for (int ks = 0; ks < 4; ks++) {
                uint32_t aF0[4], aF1[4];
                {
                    uint32_t c = (uint32_t)(kc * 8 + ks * 2 + lane16);
                    uint32_t sw = (c ^ (uint32_t)s7) << 4;
                    ldsm4(aF0, abase0 + sw);
                    ldsm4(aF1, abase1 + sw);
                }
                uint32_t b0[4], b1[4], b2[4], b3[4];
                {
                    uint32_t c = (uint32_t)(ks * 2 + lane8);
                    uint32_t sw = (c ^ (uint32_t)s7) << 4;
                    ldsm4(b0, wBase + woff0 + sw);
                    ldsm4(b1, wBase + woff1 + sw);
                    ldsm4(b2, wBase + woff2 + sw);
                    ldsm4(b3, wBase + woff3 + sw);
                }
                mma_f16(acc[0][0], aF0, b0);
                mma_f16(acc[0][1], aF0, b0 + 2);
                mma_f16(acc[0][2], aF0, b1);
                mma_f16(acc[0][3], aF0, b1 + 2);
                mma_f16(acc[0][4], aF0, b2);
                mma_f16(acc[0][5], aF0, b2 + 2);
                mma_f16(acc[0][6], aF0, b3);
                mma_f16(acc[0][7], aF0, b3 + 2);
                mma_f16(acc[1][0], aF1, b0);
                mma_f16(acc[1][1], aF1, b0 + 2);
                mma_f16(acc[1][2], aF1, b1);
                mma_f16(acc[1][3], aF1, b1 + 2);
                mma_f16(acc[1][4], aF1, b2);
                mma_f16(acc[1][5], aF1, b2 + 2);
                mma_f16(acc[1][6], aF1, b3);
                mma_f16(acc[1][7], aF1, b3 + 2);
            }
        }

        // ---- epilogue for this n-tile ----
        {
            const int colb = nt * NTILE + ng * 64 + (lane & 3) * 2;
#pragma unroll
            for (int mf = 0; mf < 2; mf++) {
#pragma unroll
                for (int nf = 0; nf < 8; nf++) {
                    int col = colb + nf * 8;
                    float q0 = qv[col], q1 = qv[col + 1];
                    float w0 = vv[col], w1 = vv[col + 1];
                    lg[mf][0] += tanh_mufu(acc[mf][nf][0] + q0) * w0
                               + tanh_mufu(acc[mf][nf][1] + q1) * w1;
                    lg[mf][1] += tanh_mufu(acc[mf][nf][2] + q0) * w0
                               + tanh_mufu(acc[mf][nf][3] + q1) * w1;
                }
            }
        }
    }

    // reduce lg across lane%4 (col groups), then across the 2 n-groups via SMEM
    float* red = reinterpret_cast<float*>(smem + SM_RED);
#pragma unroll
    for (int mf = 0; mf < 2; mf++)
#pragma unroll
        for (int h = 0; h < 2; h++) {
            float x = lg[mf][h];
            x += __shfl_xor_sync(0xffffffffu, x, 1);
            x += __shfl_xor_sync(0xffffffffu, x, 2);
            lg[mf][h] = x;
        }
    if ((lane & 3) == 0) {
        int r = mg * 32 + (lane >> 2);      // + mf*16 + h*8
        red[ng * 128 + r]      = lg[0][0];
        red[ng * 128 + r + 8]  = lg[0][1];
        red[ng * 128 + r + 16] = lg[1][0];
        red[ng * 128 + r + 24] = lg[1][1];
    }
    __syncthreads();
    if (tid < 128) {
        logits[(size_t)b * L_ + l0 + tid] = red[tid] + red[128 + tid];
    }
}

// ---------------------------------------------------------------------------
// Kernel 3: masked softmax in place
// ---------------------------------------------------------------------------
__global__ void softmax_kernel(float* __restrict__ att,
                               const int* __restrict__ length) {
    int b = blockIdx.x;
    int n = length[b];
    float* row = att + (size_t)b * L_;
    int tid = threadIdx.x;                 // 256
    __shared__ float red[8];

    float m = NEGV;
    for (int l = tid; l < n; l += 256) m = fmaxf(m, row[l]);
#pragma unroll
    for (int o = 16; o > 0; o >>= 1) m = fmaxf(m, __shfl_xor_sync(0xffffffffu, m, o));
    if ((tid & 31) == 0) red[tid >> 5] = m;
    __syncthreads();
    m = red[0];
#pragma unroll
    for (int i = 1; i < 8; i++) m = fmaxf(m, red[i]);
    __syncthreads();

    float s = 0.0f;
    for (int l = tid; l < L_; l += 256) {
        float e = (l < n) ? expf(row[l] - m) : 0.0f;
        row[l] = e;
        s += e;
    }
#pragma unroll
    for (int o = 16; o > 0; o >>= 1) s += __shfl_xor_sync(0xffffffffu, s, o);
    if ((tid & 31) == 0) red[tid >> 5] = s;
    __syncthreads();
    s = red[0];
#pragma unroll
    for (int i = 1; i < 8; i++) s += red[i];

    float inv = 1.0f / (s + EPS_);
    for (int l = tid; l < L_; l += 256) row[l] *= inv;
}

// ---------------------------------------------------------------------------
// Kernel 4: context partials (fp32 enc)
// ---------------------------------------------------------------------------
__global__ void ctx_partial_kernel(const float* __restrict__ enc,
                                   const float* __restrict__ att,
                                   const int* __restrict__ length) {
    int s = blockIdx.x;                    // 0..31
    int b = blockIdx.y;
    int t = threadIdx.x;                   // 128
    int n = length[b];
    int lbeg = s * (L_ / NSPLIT);
    int lend = lbeg + (L_ / NSPLIT);
    if (lend > n) lend = n;

    const float4* encb = reinterpret_cast<const float4*>(enc + (size_t)b * L_ * E_);
    const float* attb = att + (size_t)b * L_;
    float4 acc = make_float4(0.f, 0.f, 0.f, 0.f);
    int l = lbeg;
    for (; l + 4 <= lend; l += 4) {
#pragma unroll
        for (int u = 0; u < 4; u++) {
            float a = attb[l + u];
            float4 r = encb[(size_t)(l + u) * 128 + t];
            acc.x = fmaf(a, r.x, acc.x);
            acc.y = fmaf(a, r.y, acc.y);
            acc.z = fmaf(a, r.z, acc.z);
            acc.w = fmaf(a, r.w, acc.w);
        }
    }
    for (; l < lend; l++) {
        float a = attb[l];
        float4 r = encb[(size_t)l * 128 + t];
        acc.x = fmaf(a, r.x, acc.x);
        acc.y = fmaf(a, r.y, acc.y);
        acc.z = fmaf(a, r.z, acc.z);
        acc.w = fmaf(a, r.w, acc.w);
    }
    float4* outp = reinterpret_cast<float4*>(g_ctx_part + ((size_t)(b * NSPLIT + s)) * E_);
    outp[t] = acc;
}

// ---------------------------------------------------------------------------
// Kernel 5: reduce partials -> context
// ---------------------------------------------------------------------------
__global__ void ctx_reduce_kernel(float* __restrict__ context) {
    int b = blockIdx.x;
    int t = threadIdx.x;                   // 128
    float4 a = make_float4(0.f, 0.f, 0.f, 0.f);
#pragma unroll
    for (int s = 0; s < NSPLIT; s++) {
        const float4* p = reinterpret_cast<const float4*>(
            g_ctx_part + ((size_t)(b * NSPLIT + s)) * E_);
        float4 r = p[t];
        a.x += r.x; a.y += r.y; a.z += r.z; a.w += r.w;
    }
    reinterpret_cast<float4*>(context + (size_t)b * E_)[t] = a;
}

// ---------------------------------------------------------------------------
// launch
// ---------------------------------------------------------------------------
extern "C" void kernel_launch(void* const* d_in, const int* in_sizes, int n_in,
                              void* d_out, int out_size) {
    const float* enc   = (const float*)d_in[0];   // [B,L,E]
    const float* query = (const float*)d_in[1];   // [B,Q]
    const int*   len   = (const int*)  d_in[2];   // [B]
    const float* W1    = (const float*)d_in[3];   // [E+Q,E]
    const float* b1    = (const float*)d_in[4];   // [E]
    const float* v     = (const float*)d_in[5];   // [E]

    float* context = (float*)d_out;               // [B,E]
    float* att     = (float*)d_out + B_ * E_;     // [B,L]

    cudaFuncSetAttribute(logits_mma_kernel,
                         cudaFuncAttributeMaxDynamicSharedMemorySize, SMEM_GEMM);

    wprep_kernel<<<E_, 512>>>(W1);                       // idx 0
    {
        dim3 g(2, B_);
        qproj_kernel<<<g, 256>>>(query, W1, b1);         // idx 1
    }
    dummy_pad_kernel<<<1, 32>>>();                       // idx 2 (profiler pad)
    logits_mma_kernel<<<(B_ * L_) / BM, 256, SMEM_GEMM>>>(enc, v, len, att);  // idx 3
    softmax_kernel<<<B_, 256>>>(att, len);               // idx 4
    {
        dim3 g(NSPLIT, B_);
        ctx_partial_kernel<<<g, 128>>>(enc, att, len);   // idx 5
    }
    ctx_reduce_kernel<<<B_, 128>>>(context);             // idx 6
}

// round 13
// speedup vs baseline: 1.1195x; 1.1195x over previous
#include <cuda_runtime.h>
#include <cuda_bf16.h>
#include <cuda_fp16.h>
#include <math.h>
#include <stdint.h>

#define B_   64
#define L_   2048
#define E_   512
#define Q_   256
#define NEGV -1000000000.0f
#define EPS_ 1e-5f
#define NSPLIT 32
#define NTILES 2048          // (B_ * L_) / BM

// ---------------------------------------------------------------------------
// device scratch (no allocations allowed)
// ---------------------------------------------------------------------------
__device__ float g_qproj[B_ * E_];
__device__ float g_ctx_part[B_ * NSPLIT * E_];
__device__ __align__(16) __half g_Wt16[E_ * E_];   // W1[:E]^T fp16 [e][k]
__device__ int g_tile_ctr;

// ---------------------------------------------------------------------------
// PTX helpers
// ---------------------------------------------------------------------------
__device__ __forceinline__ uint32_t smem_u32_of(const void* p) {
    uint32_t a;
    asm("{ .reg .u64 t; cvta.to.shared.u64 t, %1; cvt.u32.u64 %0, t; }"
        : "=r"(a) : "l"(p));
    return a;
}

__device__ __forceinline__ void ldsm4(uint32_t* r, uint32_t addr) {
    asm volatile("ldmatrix.sync.aligned.m8n8.x4.shared.b16 {%0,%1,%2,%3}, [%4];"
                 : "=r"(r[0]), "=r"(r[1]), "=r"(r[2]), "=r"(r[3]) : "r"(addr));
}

__device__ __forceinline__ void mma_f16(float* c, const uint32_t* a, const uint32_t* b) {
    asm volatile(
        "mma.sync.aligned.m16n8k16.row.col.f32.f16.f16.f32 "
        "{%0,%1,%2,%3}, {%4,%5,%6,%7}, {%8,%9}, {%0,%1,%2,%3};"
        : "+f"(c[0]), "+f"(c[1]), "+f"(c[2]), "+f"(c[3])
        : "r"(a[0]), "r"(a[1]), "r"(a[2]), "r"(a[3]), "r"(b[0]), "r"(b[1]));
}

#define CP_ASYNC16(dst, src) \
    asm volatile("cp.async.cg.shared.global [%0], [%1], 16;" :: "r"(dst), "l"(src) : "memory")
#define CP_COMMIT()  asm volatile("cp.async.commit_group;" ::: "memory")
#define CP_WAITG0()  asm volatile("cp.async.wait_group 0;" ::: "memory")

// ---------------------------------------------------------------------------
// MUFU tanh: ex2.approx + rcp.approx (both <=2 ulp). ~6 instructions.
// ---------------------------------------------------------------------------
__device__ __forceinline__ float tanh_mufu(float x) {
    float xc = fminf(fmaxf(x, -9.0f), 9.0f);
    float e;
    asm("ex2.approx.f32 %0, %1;" : "=f"(e) : "f"(xc * 2.885390081777927f)); // e^{2x}
    float r;
    asm("rcp.approx.f32 %0, %1;" : "=f"(r) : "f"(e + 1.0f));
    return (e - 1.0f) * r;
}

// ---------------------------------------------------------------------------
// Kernel 0: transpose + fp16 convert of W1[:E]
// ---------------------------------------------------------------------------
__global__ void wprep_kernel(const float* __restrict__ W1) {
    int idx = blockIdx.x * 512 + threadIdx.x;    // idx = e*512 + k
    int e = idx >> 9;
    int k = idx & 511;
    g_Wt16[idx] = __float2half_rn(W1[(size_t)k * E_ + e]);
}

// ---------------------------------------------------------------------------
// Kernel 1: qproj[b,e] = b1[e] + sum_q query[b,q] * W1[E+q, e]
// grid (16, 8): x = e-slice of 32, y = b-group of 8. W1[E:] read 8x not 64x.
// ---------------------------------------------------------------------------
__global__ void qproj_kernel(const float* __restrict__ query,
                             const float* __restrict__ W1,
                             const float* __restrict__ b1) {
    __shared__ float qs[8][Q_];                 // 8 KB
    int tid = threadIdx.x;                      // 256
    int b0 = blockIdx.y * 8;
    int e  = blockIdx.x * 32 + (tid & 31);
    int bi = tid >> 5;                          // 0..7
    // load query rows b0..b0+7
    {
        int r = tid >> 5;                       // 0..7
        int c = (tid & 31) * 8;                 // 8 floats each
#pragma unroll
        for (int u = 0; u < 8; u++)
            qs[r][c + u] = query[(b0 + r) * Q_ + c + u];
    }
    __syncthreads();
    float acc = b1[e];
#pragma unroll 8
    for (int q = 0; q < Q_; q++)
        acc = fmaf(qs[bi][q], W1[(size_t)(E_ + q) * E_ + e], acc);
    g_qproj[(b0 + bi) * E_ + e] = acc;
}

// ---------------------------------------------------------------------------
// Kernel 2 (pad + reset): resets persistent work counter; keeps logits at idx 3
// ---------------------------------------------------------------------------
__global__ void reset_ctr_kernel() {
    if (threadIdx.x == 0) g_tile_ctr = 0;
}

// ---------------------------------------------------------------------------
// Kernel 3: PERSISTENT tensor-core logits, fp16 x fp16, fp32 acc.
// grid=296 (2/SM), atomic tile queue over 2048 tiles, masked tiles skipped.
// Inner loop identical to R11 best: BM=64, warp tile 32x32, A resident fp16,
// W double-buffered cp.async, 1 sync/stage, MUFU tanh epilogue.
// ---------------------------------------------------------------------------
#define BM 64
#define NTILE 128

#define SM_W    0                       // [2 stage][128 n][128B] fp16 = 32768
#define W_STAGE 16384
#define SM_A    32768                   // [64 rows][1024B] fp16 resident = 65536
#define SM_QV   98304                   // 512 floats
#define SM_VV   100352                  // 512 floats
#define SM_RED  102400                  // 256 floats
#define SM_IDX  103424                  // 1 int
#define SMEM_GEMM 103440

__global__ void __launch_bounds__(256, 2)
logits_mma_kernel(const float* __restrict__ enc,
                  const float* __restrict__ v,
                  const int* __restrict__ length,
                  float* __restrict__ logits) {
    extern __shared__ char smem[];
    uint32_t smem_b = smem_u32_of(smem);
    const int tid  = threadIdx.x;
    const int lane = tid & 31;
    const int wid  = tid >> 5;
    const int mg   = wid & 1;       // 2 M-groups of 32 rows
    const int ng   = wid >> 1;      // 4 N-groups of 32 cols

    // ---- tile-independent precomputed bases ----
    const __half* wsrc0 = g_Wt16 + (size_t)(tid >> 3) * E_ + (tid & 7) * 8;
    const uint32_t wdst0 = smem_b + SM_W + (uint32_t)(tid >> 3) * 128
                         + (((uint32_t)((tid & 7) ^ ((tid >> 3) & 7))) << 4);
    const int  s7     = lane & 7;
    const int  lane16 = lane >> 4;
    const int  lane8  = (lane >> 3) & 1;
    const int  arow0  = mg * 32 + (lane & 15);
    const uint32_t abase0 = smem_b + SM_A + (uint32_t)arow0 * 1024;
    const uint32_t abase1 = abase0 + 16 * 1024;
    const int  nr     = ng * 32 + (lane & 7) + (lane16 << 3);
    const uint32_t woff0 = (uint32_t)nr * 128;
    const uint32_t woff1 = woff0 + 16 * 128;

    int* sIdx = reinterpret_cast<int*>(smem + SM_IDX);
    float* qv = reinterpret_cast<float*>(smem + SM_QV);
    float* vv = reinterpret_cast<float*>(smem + SM_VV);
    float* red = reinterpret_cast<float*>(smem + SM_RED);

    for (;;) {
        if (tid == 0) *sIdx = atomicAdd(&g_tile_ctr, 1);
        __syncthreads();
        const int idx = *sIdx;
        __syncthreads();                 // protect sIdx from next overwrite
        if (idx >= NTILES) break;

        const int b  = idx >> 5;
        const int l0 = (idx & 31) * BM;
        if (l0 >= length[b]) continue;   // masked tile: softmax zeroes it anyway

        // prefetch W stage 0 (overlaps A conversion)
#pragma unroll
        for (int i = 0; i < 4; i++)
            CP_ASYNC16(wdst0 + i * 4096, wsrc0 + i * 16384);
        CP_COMMIT();

        // epilogue constants
        qv[tid]       = g_qproj[b * E_ + tid];
        qv[tid + 256] = g_qproj[b * E_ + tid + 256];
        vv[tid]       = v[tid];
        vv[tid + 256] = v[tid + 256];

        // ---- A resident: 64 rows x 512 k fp32 -> fp16, once per tile ----
        const float* Ag = enc + ((size_t)b * L_ + l0) * E_;
#pragma unroll
        for (int i = 0; i < 32; i++) {
            int ii  = i * 256 + tid;
            int row = ii >> 7;
            int f4  = ii & 127;
            float4 a = *reinterpret_cast<const float4*>(Ag + (size_t)row * E_ + f4 * 4);
            __half2 h0 = __floats2half2_rn(a.x, a.y);
            __half2 h1 = __floats2half2_rn(a.z, a.w);
            uint32_t off = (uint32_t)(row * 1024)
                         + ((uint32_t)(((f4 >> 1) ^ (row & 7))) << 4) + (f4 & 1) * 8;
            *reinterpret_cast<__half2*>(smem + SM_A + off)     = h0;
            *reinterpret_cast<__half2*>(smem + SM_A + off + 4) = h1;
        }

        float acc[2][4][4];
        float lg[2][2] = {{0.f, 0.f}, {0.f, 0.f}};

        for (int nt = 0; nt < 4; nt++) {
#pragma unroll
            for (int mf = 0; mf < 2; mf++)
#pragma unroll
                for (int nf = 0; nf < 4; nf++)
#pragma unroll
                    for (int e = 0; e < 4; e++) acc[mf][nf][e] = 0.0f;

#pragma unroll
            for (int kc = 0; kc < 8; kc++) {
                const int s = nt * 8 + kc;

                CP_WAITG0();
                __syncthreads();

                if (s + 1 < 32) {
                    const int sn = s + 1;
                    const uint32_t srcoff = (uint32_t)(sn >> 3) * 65536u
                                          + (uint32_t)(sn & 7) * 64u;   // in halfs
                    const uint32_t dstb = wdst0 + (uint32_t)(sn & 1) * W_STAGE;
#pragma unroll
                    for (int i = 0; i < 4; i++)
                        CP_ASYNC16(dstb + i * 4096, wsrc0 + srcoff + i * 16384);
                    CP_COMMIT();
                }

                const uint32_t wBase = smem_b + SM_W + (uint32_t)(s & 1) * W_STAGE;

#pragma unroll
                for (int ks = 0; ks < 4; ks++) {
                    uint32_t aF0[4], aF1[4];
                    {
                        uint32_t c = (uint32_t)(kc * 8 + ks * 2 + lane16);
                        uint32_t sw = (c ^ (uint32_t)s7) << 4;
                        ldsm4(aF0, abase0 + sw);
                        ldsm4(aF1, abase1 + sw);
                    }
                    uint32_t b0[4], b1[4];
                    {
                        uint32_t c = (uint32_t)(ks * 2 + lane8);
                        uint32_t sw = (c ^ (uint32_t)s7) << 4;
                        ldsm4(b0, wBase + woff0 + sw);
                        ldsm4(b1, wBase + woff1 + sw);
                    }
                    mma_f16(acc[0][0], aF0, b0);
                    mma_f16(acc[0][1], aF0, b0 + 2);
                    mma_f16(acc[0][2], aF0, b1);
                    mma_f16(acc[0][3], aF0, b1 + 2);
                    mma_f16(acc[1][0], aF1, b0);
                    mma_f16(acc[1][1], aF1, b0 + 2);
                    mma_f16(acc[1][2], aF1, b1);
                    mma_f16(acc[1][3], aF1, b1 + 2);
                }
            }

            // ---- epilogue for this n-tile ----
            {
                const int colb = nt * NTILE + ng * 32 + (lane & 3) * 2;
#pragma unroll
                for (int mf = 0; mf < 2; mf++) {
#pragma unroll
                    for (int nf = 0; nf < 4; nf++) {
                        int col = colb + nf * 8;
                        float q0 = qv[col], q1 = qv[col + 1];
                        float w0 = vv[col], w1 = vv[col + 1];
                        lg[mf][0] += tanh_mufu(acc[mf][nf][0] + q0) * w0
                                   + tanh_mufu(acc[mf][nf][1] + q1) * w1;
                        lg[mf][1] += tanh_mufu(acc[mf][nf][2] + q0) * w0
                                   + tanh_mufu(acc[mf][nf][3] + q1) * w1;
                    }
                }
            }
        }

        // reduce lg across lane%4, then across the 4 n-groups via SMEM
#pragma unroll
        for (int mf = 0; mf < 2; mf++)
#pragma unroll
            for (int h = 0; h < 2; h++) {
                float x = lg[mf][h];
                x += __shfl_xor_sync(0xffffffffu, x, 1);
                x += __shfl_xor_sync(0xffffffffu, x, 2);
                lg[mf][h] = x;
            }
        if ((lane & 3) == 0) {
            int r = mg * 32 + (lane >> 2);
            red[ng * 64 + r]      = lg[0][0];
            red[ng * 64 + r + 8]  = lg[0][1];
            red[ng * 64 + r + 16] = lg[1][0];
            red[ng * 64 + r + 24] = lg[1][1];
        }
        __syncthreads();
        if (tid < 64) {
            logits[(size_t)b * L_ + l0 + tid] =
                red[tid] + red[64 + tid] + red[128 + tid] + red[192 + tid];
        }
        __syncthreads();                 // red[] reuse + loop back safety
    }
}

// ---------------------------------------------------------------------------
// Kernel 4: masked softmax in place
// ---------------------------------------------------------------------------
__global__ void softmax_kernel(float* __restrict__ att,
                               const int* __restrict__ length) {
    int b = blockIdx.x;
    int n = length[b];
    float* row = att + (size_t)b * L_;
    int tid = threadIdx.x;                 // 256
    __shared__ float red[8];

    float m = NEGV;
    for (int l = tid; l < n; l += 256) m = fmaxf(m, row[l]);
#pragma unroll
    for (int o = 16; o > 0; o >>= 1) m = fmaxf(m, __shfl_xor_sync(0xffffffffu, m, o));
    if ((tid & 31) == 0) red[tid >> 5] = m;
    __syncthreads();
    m = red[0];
#pragma unroll
    for (int i = 1; i < 8; i++) m = fmaxf(m, red[i]);
    __syncthreads();

    float s = 0.0f;
    for (int l = tid; l < L_; l += 256) {
        float e = (l < n) ? expf(row[l] - m) : 0.0f;
        row[l] = e;
        s += e;
    }
#pragma unroll
    for (int o = 16; o > 0; o >>= 1) s += __shfl_xor_sync(0xffffffffu, s, o);
    if ((tid & 31) == 0) red[tid >> 5] = s;
    __syncthreads();
    s = red[0];
#pragma unroll
    for (int i = 1; i < 8; i++) s += red[i];

    float inv = 1.0f / (s + EPS_);
    for (int l = tid; l < L_; l += 256) row[l] *= inv;
}

// ---------------------------------------------------------------------------
// Kernel 5: context partials (fp32 enc)
// ---------------------------------------------------------------------------
__global__ void ctx_partial_kernel(const float* __restrict__ enc,
                                   const float* __restrict__ att,
                                   const int* __restrict__ length) {
    int s = blockIdx.x;                    // 0..31
    int b = blockIdx.y;
    int t = threadIdx.x;                   // 128
    int n = length[b];
    int lbeg = s * (L_ / NSPLIT);
    int lend = lbeg + (L_ / NSPLIT);
    if (lend > n) lend = n;

    const float4* encb = reinterpret_cast<const float4*>(enc + (size_t)b * L_ * E_);
    const float* attb = att + (size_t)b * L_;
    float4 acc = make_float4(0.f, 0.f, 0.f, 0.f);
    int l = lbeg;
    for (; l + 4 <= lend; l += 4) {
#pragma unroll
        for (int u = 0; u < 4; u++) {
            float a = attb[l + u];
            float4 r = encb[(size_t)(l + u) * 128 + t];
            acc.x = fmaf(a, r.x, acc.x);
            acc.y = fmaf(a, r.y, acc.y);
            acc.z = fmaf(a, r.z, acc.z);
            acc.w = fmaf(a, r.w, acc.w);
        }
    }
    for (; l < lend; l++) {
        float a = attb[l];
        float4 r = encb[(size_t)l * 128 + t];
        acc.x = fmaf(a, r.x, acc.x);
        acc.y = fmaf(a, r.y, acc.y);
        acc.z = fmaf(a, r.z, acc.z);
        acc.w = fmaf(a, r.w, acc.w);
    }
    float4* outp = reinterpret_cast<float4*>(g_ctx_part + ((size_t)(b * NSPLIT + s)) * E_);
    outp[t] = acc;
}

// ---------------------------------------------------------------------------
// Kernel 6: reduce partials -> context
// ---------------------------------------------------------------------------
__global__ void ctx_reduce_kernel(float* __restrict__ context) {
    int b = blockIdx.x;
    int t = threadIdx.x;                   // 128
    float4 a = make_float4(0.f, 0.f, 0.f, 0.f);
#pragma unroll
    for (int s = 0; s < NSPLIT; s++) {
        const float4* p = reinterpret_cast<const float4*>(
            g_ctx_part + ((size_t)(b * NSPLIT + s)) * E_);
        float4 r = p[t];
        a.x += r.x; a.y += r.y; a.z += r.z; a.w += r.w;
    }
    reinterpret_cast<float4*>(context + (size_t)b * E_)[t] = a;
}

// ---------------------------------------------------------------------------
// launch
// ---------------------------------------------------------------------------
extern "C" void kernel_launch(void* const* d_in, const int* in_sizes, int n_in,
                              void* d_out, int out_size) {
    const float* enc   = (const float*)d_in[0];   // [B,L,E]
    const float* query = (const float*)d_in[1];   // [B,Q]
    const int*   len   = (const int*)  d_in[2];   // [B]
    const float* W1    = (const float*)d_in[3];   // [E+Q,E]
    const float* b1    = (const float*)d_in[4];   // [E]
    const float* v     = (const float*)d_in[5];   // [E]

    float* context = (float*)d_out;               // [B,E]
    float* att     = (float*)d_out + B_ * E_;     // [B,L]

    cudaFuncSetAttribute(logits_mma_kernel,
                         cudaFuncAttributeMaxDynamicSharedMemorySize, SMEM_GEMM);

    wprep_kernel<<<E_, 512>>>(W1);                       // idx 0
    {
        dim3 g(16, 8);
        qproj_kernel<<<g, 256>>>(query, W1, b1);         // idx 1
    }
    reset_ctr_kernel<<<1, 32>>>();                       // idx 2 (pad + reset)
    logits_mma_kernel<<<296, 256, SMEM_GEMM>>>(enc, v, len, att);  // idx 3
    softmax_kernel<<<B_, 256>>>(att, len);               // idx 4
    {
        dim3 g(NSPLIT, B_);
        ctx_partial_kernel<<<g, 128>>>(enc, att, len);   // idx 5
    }
    ctx_reduce_kernel<<<B_, 128>>>(context);             // idx 6
}

// round 14
// speedup vs baseline: 1.1663x; 1.0418x over previous
#include <cuda_runtime.h>
#include <cuda_bf16.h>
#include <cuda_fp16.h>
#include <math.h>
#include <stdint.h>

#define B_   64
#define L_   2048
#define E_   512
#define Q_   256
#define NEGV -1000000000.0f
#define EPS_ 1e-5f
#define NSPLIT 32

// ---------------------------------------------------------------------------
// device scratch (no allocations allowed)
// ---------------------------------------------------------------------------
__device__ float g_qproj[B_ * E_];
__device__ float g_ctx_part[B_ * NSPLIT * E_];
__device__ __align__(16) __half g_Wt16[E_ * E_];   // W1[:E]^T fp16 [e][k]
__device__ int g_dummy_sink;

// ---------------------------------------------------------------------------
// PTX helpers
// ---------------------------------------------------------------------------
__device__ __forceinline__ uint32_t smem_u32_of(const void* p) {
    uint32_t a;
    asm("{ .reg .u64 t; cvta.to.shared.u64 t, %1; cvt.u32.u64 %0, t; }"
        : "=r"(a) : "l"(p));
    return a;
}

__device__ __forceinline__ void ldsm4(uint32_t* r, uint32_t addr) {
    asm volatile("ldmatrix.sync.aligned.m8n8.x4.shared.b16 {%0,%1,%2,%3}, [%4];"
                 : "=r"(r[0]), "=r"(r[1]), "=r"(r[2]), "=r"(r[3]) : "r"(addr));
}

__device__ __forceinline__ void mma_f16(float* c, const uint32_t* a, const uint32_t* b) {
    asm volatile(
        "mma.sync.aligned.m16n8k16.row.col.f32.f16.f16.f32 "
        "{%0,%1,%2,%3}, {%4,%5,%6,%7}, {%8,%9}, {%0,%1,%2,%3};"
        : "+f"(c[0]), "+f"(c[1]), "+f"(c[2]), "+f"(c[3])
        : "r"(a[0]), "r"(a[1]), "r"(a[2]), "r"(a[3]), "r"(b[0]), "r"(b[1]));
}

#define CP_ASYNC16(dst, src) \
    asm volatile("cp.async.cg.shared.global [%0], [%1], 16;" :: "r"(dst), "l"(src) : "memory")
#define CP_COMMIT()  asm volatile("cp.async.commit_group;" ::: "memory")
#define CP_WAITG0()  asm volatile("cp.async.wait_group 0;" ::: "memory")
#define BAR_PAIR(id) asm volatile("bar.sync %0, 64;" :: "r"(id) : "memory")

// ---------------------------------------------------------------------------
// MUFU tanh
// ---------------------------------------------------------------------------
__device__ __forceinline__ float tanh_mufu(float x) {
    float xc = fminf(fmaxf(x, -9.0f), 9.0f);
    float e;
    asm("ex2.approx.f32 %0, %1;" : "=f"(e) : "f"(xc * 2.885390081777927f)); // e^{2x}
    float r;
    asm("rcp.approx.f32 %0, %1;" : "=f"(r) : "f"(e + 1.0f));
    return (e - 1.0f) * r;
}

// ---------------------------------------------------------------------------
// Kernel 0: transpose + fp16 convert of W1[:E]
// ---------------------------------------------------------------------------
__global__ void wprep_kernel(const float* __restrict__ W1) {
    int idx = blockIdx.x * 512 + threadIdx.x;    // idx = e*512 + k
    int e = idx >> 9;
    int k = idx & 511;
    g_Wt16[idx] = __float2half_rn(W1[(size_t)k * E_ + e]);
}

// ---------------------------------------------------------------------------
// Kernel 1: qproj — grid (16, 8): W1[E:] read 8x not 64x
// ---------------------------------------------------------------------------
__global__ void qproj_kernel(const float* __restrict__ query,
                             const float* __restrict__ W1,
                             const float* __restrict__ b1) {
    __shared__ float qs[8][Q_];
    int tid = threadIdx.x;                      // 256
    int b0 = blockIdx.y * 8;
    int e  = blockIdx.x * 32 + (tid & 31);
    int bi = tid >> 5;
    {
        int r = tid >> 5;
        int c = (tid & 31) * 8;
#pragma unroll
        for (int u = 0; u < 8; u++)
            qs[r][c + u] = query[(b0 + r) * Q_ + c + u];
    }
    __syncthreads();
    float acc = b1[e];
#pragma unroll 8
    for (int q = 0; q < Q_; q++)
        acc = fmaf(qs[bi][q], W1[(size_t)(E_ + q) * E_ + e], acc);
    g_qproj[(b0 + bi) * E_ + e] = acc;
}

// ---------------------------------------------------------------------------
// Dummy pad kernel (positions logits at profiled launch index 3)
// ---------------------------------------------------------------------------
__global__ void dummy_pad_kernel() {
    if (threadIdx.x == 0) g_dummy_sink = 1;
}

// ---------------------------------------------------------------------------
// Kernel 2: tensor-core logits, fp16 x fp16, fp32 acc. BM=64, warp tile 32x32.
// PAIR-PRIVATE W buffers: each ng warp-pair owns a double-buffered 4KB stage
// of its own 32 W rows; stage sync via named bar.sync(1+ng, 64) — NO full-CTA
// syncs in the mainloop. A resident fp16. Early exit on masked tiles.
// ---------------------------------------------------------------------------
#define BM 64
#define NTILE 128

#define SM_W    0                       // [4 pair][2 stage][32 n][128B] = 32768
#define W_PAIR  8192
#define W_STAGE 4096
#define SM_A    32768                   // [64 rows][1024B] fp16 resident = 65536
#define SM_QV   98304                   // 512 floats
#define SM_VV   100352                  // 512 floats
#define SM_RED  102400                  // 256 floats
#define SMEM_GEMM 103424

__global__ void __launch_bounds__(256, 2)
logits_mma_kernel(const float* __restrict__ enc,
                  const float* __restrict__ v,
                  const int* __restrict__ length,
                  float* __restrict__ logits) {
    extern __shared__ char smem[];
    uint32_t smem_b = smem_u32_of(smem);
    const int tid  = threadIdx.x;
    const int lane = tid & 31;
    const int wid  = tid >> 5;
    const int mg   = wid & 1;       // 2 M-groups of 32 rows
    const int ng   = wid >> 1;      // 4 N-groups of 32 cols  (= pair id)

    const int bid = blockIdx.x;     // 2048 CTAs
    const int b   = bid >> 5;
    const int l0  = (bid & 31) * BM;

    // ---- early exit: fully masked tile; softmax zeroes it anyway ----
    if (l0 >= length[b]) return;

    // ---- pair-local cp.async bases: t = tid & 63 covers 32 rows x 8 units ----
    const int t = tid & 63;                      // pair-local thread
    const int tng = tid >> 6;                    // pair id (== ng of this warp)
    const __half* wsrc0 = g_Wt16 + (size_t)(tng * 32 + (t >> 1)) * E_ + (t & 1) * 32;
    uint32_t wdsts[4];
#pragma unroll
    for (int i = 0; i < 4; i++) {
        uint32_t u = (uint32_t)((t & 1) * 4 + i);
        wdsts[i] = smem_b + SM_W + (uint32_t)tng * W_PAIR + (uint32_t)(t >> 1) * 128
                 + ((u ^ ((uint32_t)(t >> 1) & 7)) << 4);
    }

    // prefetch W stage 0 (overlaps A conversion)
#pragma unroll
    for (int i = 0; i < 4; i++)
        CP_ASYNC16(wdsts[i], wsrc0 + i * 8);     // +8 halfs = +16B
    CP_COMMIT();

    // epilogue constants
    float* qv = reinterpret_cast<float*>(smem + SM_QV);
    float* vv = reinterpret_cast<float*>(smem + SM_VV);
    qv[tid]       = g_qproj[b * E_ + tid];
    qv[tid + 256] = g_qproj[b * E_ + tid + 256];
    vv[tid]       = v[tid];
    vv[tid + 256] = v[tid + 256];

    // ---- A resident: 64 rows x 512 k fp32 -> fp16, ONCE ----
    const float* Ag = enc + ((size_t)b * L_ + l0) * E_;
#pragma unroll
    for (int i = 0; i < 32; i++) {
        int idx = i * 256 + tid;
        int row = idx >> 7;
        int f4  = idx & 127;
        float4 a = *reinterpret_cast<const float4*>(Ag + (size_t)row * E_ + f4 * 4);
        __half2 h0 = __floats2half2_rn(a.x, a.y);
        __half2 h1 = __floats2half2_rn(a.z, a.w);
        uint32_t off = (uint32_t)(row * 1024)
                     + ((uint32_t)(((f4 >> 1) ^ (row & 7))) << 4) + (f4 & 1) * 8;
        *reinterpret_cast<__half2*>(smem + SM_A + off)     = h0;
        *reinterpret_cast<__half2*>(smem + SM_A + off + 4) = h1;
    }
    __syncthreads();   // A + qv/vv visible to all warps

    // ---- precomputed ldsm bases ----
    const int  s7     = lane & 7;
    const int  lane16 = lane >> 4;
    const int  lane8  = (lane >> 3) & 1;
    const int  arow0  = mg * 32 + (lane & 15);
    const uint32_t abase0 = smem_b + SM_A + (uint32_t)arow0 * 1024;
    const uint32_t abase1 = abase0 + 16 * 1024;
    const int  nrl    = (lane & 7) + (lane16 << 3);        // pair-local row 0..15
    const uint32_t wpair = smem_b + SM_W + (uint32_t)ng * W_PAIR;
    const uint32_t woff0 = (uint32_t)nrl * 128;
    const uint32_t woff1 = woff0 + 16 * 128;

    float acc[2][4][4];
    float lg[2][2] = {{0.f, 0.f}, {0.f, 0.f}};

    for (int nt = 0; nt < 4; nt++) {
#pragma unroll
        for (int mf = 0; mf < 2; mf++)
#pragma unroll
            for (int nf = 0; nf < 4; nf++)
#pragma unroll
                for (int e = 0; e < 4; e++) acc[mf][nf][e] = 0.0f;

#pragma unroll
        for (int kc = 0; kc < 8; kc++) {
            const int s = nt * 8 + kc;

            CP_WAITG0();                 // own stage-s loads landed
            BAR_PAIR(1 + ng);            // partner's landed + done reading s-1

            // issue next stage into buffer (s+1)&1 (freed by the barrier)
            if (s + 1 < 32) {
                const int sn = s + 1;
                const uint32_t srcoff = (uint32_t)(sn >> 3) * 65536u
                                      + (uint32_t)(sn & 7) * 64u;   // in halfs
                const uint32_t stoff = (uint32_t)(sn & 1) * W_STAGE;
#pragma unroll
                for (int i = 0; i < 4; i++)
                    CP_ASYNC16(wdsts[i] + stoff, wsrc0 + srcoff + i * 8);
                CP_COMMIT();
            }

            const uint32_t wBase = wpair + (uint32_t)(s & 1) * W_STAGE;

#pragma unroll
            for (int ks = 0; ks < 4; ks++) {
                uint32_t aF0[4], aF1[4];
                {
                    uint32_t c = (uint32_t)(kc * 8 + ks * 2 + lane16);
                    uint32_t sw = (c ^ (uint32_t)s7) << 4;
                    ldsm4(aF0, abase0 + sw);
                    ldsm4(aF1, abase1 + sw);
                }
                uint32_t b0[4], b1[4];
                {
                    uint32_t c = (uint32_t)(ks * 2 + lane8);
                    uint32_t sw = (c ^ (uint32_t)(nrl & 7)) << 4;
                    ldsm4(b0, wBase + woff0 + sw);
                    ldsm4(b1, wBase + woff1 + sw);
                }
                mma_f16(acc[0][0], aF0, b0);
                mma_f16(acc[0][1], aF0, b0 + 2);
                mma_f16(acc[0][2], aF0, b1);
                mma_f16(acc[0][3], aF0, b1 + 2);
                mma_f16(acc[1][0], aF1, b0);
                mma_f16(acc[1][1], aF1, b0 + 2);
                mma_f16(acc[1][2], aF1, b1);
                mma_f16(acc[1][3], aF1, b1 + 2);
            }
        }

        // ---- epilogue for this n-tile (no sync needed: acc is private) ----
        {
            const int colb = nt * NTILE + ng * 32 + (lane & 3) * 2;
#pragma unroll
            for (int mf = 0; mf < 2; mf++) {
#pragma unroll
                for (int nf = 0; nf < 4; nf++) {
                    int col = colb + nf * 8;
                    float q0 = qv[col], q1 = qv[col + 1];
                    float w0 = vv[col], w1 = vv[col + 1];
                    lg[mf][0] += tanh_mufu(acc[mf][nf][0] + q0) * w0
                               + tanh_mufu(acc[mf][nf][1] + q1) * w1;
                    lg[mf][1] += tanh_mufu(acc[mf][nf][2] + q0) * w0
                               + tanh_mufu(acc[mf][nf][3] + q1) * w1;
                }
            }
        }
    }

    // reduce lg across lane%4, then across the 4 n-groups via SMEM
    float* red = reinterpret_cast<float*>(smem + SM_RED);
#pragma unroll
    for (int mf = 0; mf < 2; mf++)
#pragma unroll
        for (int h = 0; h < 2; h++) {
            float x = lg[mf][h];
            x += __shfl_xor_sync(0xffffffffu, x, 1);
            x += __shfl_xor_sync(0xffffffffu, x, 2);
            lg[mf][h] = x;
        }
    if ((lane & 3) == 0) {
        int r = mg * 32 + (lane >> 2);
        red[ng * 64 + r]      = lg[0][0];
        red[ng * 64 + r + 8]  = lg[0][1];
        red[ng * 64 + r + 16] = lg[1][0];
        red[ng * 64 + r + 24] = lg[1][1];
    }
    __syncthreads();
    if (tid < 64) {
        logits[(size_t)b * L_ + l0 + tid] =
            red[tid] + red[64 + tid] + red[128 + tid] + red[192 + tid];
    }
}

// ---------------------------------------------------------------------------
// Kernel 3: masked softmax in place
// ---------------------------------------------------------------------------
__global__ void softmax_kernel(float* __restrict__ att,
                               const int* __restrict__ length) {
    int b = blockIdx.x;
    int n = length[b];
    float* row = att + (size_t)b * L_;
    int tid = threadIdx.x;                 // 256
    __shared__ float red[8];

    float m = NEGV;
    for (int l = tid; l < n; l += 256) m = fmaxf(m, row[l]);
#pragma unroll
    for (int o = 16; o > 0; o >>= 1) m = fmaxf(m, __shfl_xor_sync(0xffffffffu, m, o));
    if ((tid & 31) == 0) red[tid >> 5] = m;
    __syncthreads();
    m = red[0];
#pragma unroll
    for (int i = 1; i < 8; i++) m = fmaxf(m, red[i]);
    __syncthreads();

    float s = 0.0f;
    for (int l = tid; l < L_; l += 256) {
        float e = (l < n) ? expf(row[l] - m) : 0.0f;
        row[l] = e;
        s += e;
    }
#pragma unroll
    for (int o = 16; o > 0; o >>= 1) s += __shfl_xor_sync(0xffffffffu, s, o);
    if ((tid & 31) == 0) red[tid >> 5] = s;
    __syncthreads();
    s = red[0];
#pragma unroll
    for (int i = 1; i < 8; i++) s += red[i];

    float inv = 1.0f / (s + EPS_);
    for (int l = tid; l < L_; l += 256) row[l] *= inv;
}

// ---------------------------------------------------------------------------
// Kernel 4: context partials (fp32 enc)
// ---------------------------------------------------------------------------
__global__ void ctx_partial_kernel(const float* __restrict__ enc,
                                   const float* __restrict__ att,
                                   const int* __restrict__ length) {
    int s = blockIdx.x;                    // 0..31
    int b = blockIdx.y;
    int t = threadIdx.x;                   // 128
    int n = length[b];
    int lbeg = s * (L_ / NSPLIT);
    int lend = lbeg + (L_ / NSPLIT);
    if (lend > n) lend = n;

    const float4* encb = reinterpret_cast<const float4*>(enc + (size_t)b * L_ * E_);
    const float* attb = att + (size_t)b * L_;
    float4 acc = make_float4(0.f, 0.f, 0.f, 0.f);
    int l = lbeg;
    for (; l + 4 <= lend; l += 4) {
#pragma unroll
        for (int u = 0; u < 4; u++) {
            float a = attb[l + u];
            float4 r = encb[(size_t)(l + u) * 128 + t];
            acc.x = fmaf(a, r.x, acc.x);
            acc.y = fmaf(a, r.y, acc.y);
            acc.z = fmaf(a, r.z, acc.z);
            acc.w = fmaf(a, r.w, acc.w);
        }
    }
    for (; l < lend; l++) {
        float a = attb[l];
        float4 r = encb[(size_t)l * 128 + t];
        acc.x = fmaf(a, r.x, acc.x);
        acc.y = fmaf(a, r.y, acc.y);
        acc.z = fmaf(a, r.z, acc.z);
        acc.w = fmaf(a, r.w, acc.w);
    }
    float4* outp = reinterpret_cast<float4*>(g_ctx_part + ((size_t)(b * NSPLIT + s)) * E_);
    outp[t] = acc;
}

// ---------------------------------------------------------------------------
// Kernel 5: reduce partials -> context
// ---------------------------------------------------------------------------
__global__ void ctx_reduce_kernel(float* __restrict__ context) {
    int b = blockIdx.x;
    int t = threadIdx.x;                   // 128
    float4 a = make_float4(0.f, 0.f, 0.f, 0.f);
#pragma unroll
    for (int s = 0; s < NSPLIT; s++) {
        const float4* p = reinterpret_cast<const float4*>(
            g_ctx_part + ((size_t)(b * NSPLIT + s)) * E_);
        float4 r = p[t];
        a.x += r.x; a.y += r.y; a.z += r.z; a.w += r.w;
    }
    reinterpret_cast<float4*>(context + (size_t)b * E_)[t] = a;
}

// ---------------------------------------------------------------------------
// launch
// ---------------------------------------------------------------------------
extern "C" void kernel_launch(void* const* d_in, const int* in_sizes, int n_in,
                              void* d_out, int out_size) {
    const float* enc   = (const float*)d_in[0];   // [B,L,E]
    const float* query = (const float*)d_in[1];   // [B,Q]
    const int*   len   = (const int*)  d_in[2];   // [B]
    const float* W1    = (const float*)d_in[3];   // [E+Q,E]
    const float* b1    = (const float*)d_in[4];   // [E]
    const float* v     = (const float*)d_in[5];   // [E]

    float* context = (float*)d_out;               // [B,E]
    float* att     = (float*)d_out + B_ * E_;     // [B,L]

    cudaFuncSetAttribute(logits_mma_kernel,
                         cudaFuncAttributeMaxDynamicSharedMemorySize, SMEM_GEMM);

    wprep_kernel<<<E_, 512>>>(W1);                       // idx 0
    {
        dim3 g(16, 8);
        qproj_kernel<<<g, 256>>>(query, W1, b1);         // idx 1
    }
    dummy_pad_kernel<<<1, 32>>>();                       // idx 2 (profiler pad)
    logits_mma_kernel<<<(B_ * L_) / BM, 256, SMEM_GEMM>>>(enc, v, len, att);  // idx 3
    softmax_kernel<<<B_, 256>>>(att, len);               // idx 4
    {
        dim3 g(NSPLIT, B_);
        ctx_partial_kernel<<<g, 128>>>(enc, att, len);   // idx 5
    }
    ctx_reduce_kernel<<<B_, 128>>>(context);             // idx 6
}